// round 1
// baseline (speedup 1.0000x reference)
#include <cuda_runtime.h>
#include <math.h>

#define Bsz 32
#define Rr  256
#define Tt  512
#define Cc  16
#define NC1 64
#define NC2 128

// ---- scratch (static __device__ per allocation rules) ----
__device__ float g_z[67108864];        // [B][C][R][T]  z = (x-mean)*rsqrt(sumsq), 268MB
__device__ float g_epart[8388608];     // [B*C][R][C1]  partial e per (b,c), 33.5MB
__device__ float g_e[524288];          // [B][R][C1]    e after bias+leakyrelu
__device__ float g_pooled[8192];       // [B][R]

// ============================================================
// K1: per (b,r): load x[b,r,:,:] (512x16), compute per-c mean & inv-norm,
//     write z[b,c,r,:] transposed.
// ============================================================
__global__ void k_stats(const float* __restrict__ x) {
    int br = blockIdx.x;                 // b*R + r
    int b = br >> 8, r = br & 255;
    __shared__ float sx[Cc * 513];
    __shared__ float red[256];
    __shared__ float s_mean[Cc], s_inv[Cc];
    const float* xp = x + (size_t)br * (Tt * Cc);
    int tid = threadIdx.x;

    #pragma unroll
    for (int i = 0; i < 8; i++) {
        int idx4 = tid + i * 256;                 // 0..2047 float4s
        int t = idx4 >> 2;
        int c0 = (idx4 & 3) * 4;
        float4 v = *(const float4*)(xp + idx4 * 4);
        sx[(c0 + 0) * 513 + t] = v.x;
        sx[(c0 + 1) * 513 + t] = v.y;
        sx[(c0 + 2) * 513 + t] = v.z;
        sx[(c0 + 3) * 513 + t] = v.w;
    }
    __syncthreads();

    int c = tid & 15, seg = tid >> 4;
    float p = 0.f;
    #pragma unroll
    for (int u = 0; u < 32; u++) p += sx[c * 513 + seg * 32 + u];
    red[seg * 16 + c] = p;
    __syncthreads();
    if (tid < 16) {
        float s = 0.f;
        #pragma unroll
        for (int sg = 0; sg < 16; sg++) s += red[sg * 16 + tid];
        s_mean[tid] = s * (1.0f / Tt);
    }
    __syncthreads();

    float mc = s_mean[c];
    p = 0.f;
    #pragma unroll
    for (int u = 0; u < 32; u++) {
        float d = sx[c * 513 + seg * 32 + u] - mc;
        p += d * d;
    }
    red[seg * 16 + c] = p;
    __syncthreads();
    if (tid < 16) {
        float s = 0.f;
        #pragma unroll
        for (int sg = 0; sg < 16; sg++) s += red[sg * 16 + tid];
        s_inv[tid] = rsqrtf(s);
    }
    __syncthreads();

    int cw = tid >> 4, t0 = tid & 15;
    float m = s_mean[cw], inv = s_inv[cw];
    float* zo = g_z + (((size_t)b * Cc + cw) * Rr + r) * Tt;
    #pragma unroll
    for (int j = 0; j < 32; j++) {
        int t = t0 + j * 16;
        zo[t] = (sx[cw * 513 + t] - m) * inv;
    }
}

// ============================================================
// K2: per (b,c): stream z in T-chunks of 32.
//   GEMM1: y[t][o] = sum_k W[o][k] * z[k][t]
//   GEMM2: epart[r][o] += sum_t z[r][t] * y[t][o]
// ============================================================
__global__ __launch_bounds__(256, 2) void k_gemm(const float* __restrict__ W_edge) {
    extern __shared__ float sm[];
    float* Ws = sm;                       // [64][256]
    float* Zs = sm + 64 * 256;            // [32][257]  (Zs[t*257+r])
    float* Ys = Zs + 32 * 257;            // [32][68]   (Ys[t*68+o])
    int bc = blockIdx.x;                  // b*16 + c
    int c = bc & 15;
    int tid = threadIdx.x;
    const float* zb = g_z + (size_t)bc * (Rr * Tt);

    // Load W_edge[:, c, :] once: Ws[o][k]
    #pragma unroll
    for (int i = 0; i < 16; i++) {
        int idx4 = tid + i * 256;          // 0..4095
        int o = idx4 >> 6, k4 = idx4 & 63;
        float4 v = *(const float4*)(W_edge + ((size_t)o * Cc + c) * Rr + k4 * 4);
        *(float4*)(Ws + o * 256 + k4 * 4) = v;
    }

    float acc[64];
    #pragma unroll
    for (int o = 0; o < 64; o++) acc[o] = 0.f;

    int tt = tid & 31;        // t index for GEMM1 (lane)
    int og = tid >> 5;        // o-group (warp id)
    int r = tid;              // row owned in GEMM2

    for (int ch = 0; ch < 16; ch++) {
        __syncthreads();   // also covers initial Ws load + prev GEMM2 done with Zs
        // ---- fill Zs[t][r] = z[b,c,r, ch*32+t] ----
        #pragma unroll
        for (int i = 0; i < 8; i++) {
            int idx4 = tid + i * 256;      // 0..2047
            int rr = idx4 >> 3, t4 = idx4 & 7;
            float4 v = *(const float4*)(zb + rr * Tt + ch * 32 + t4 * 4);
            Zs[(t4 * 4 + 0) * 257 + rr] = v.x;
            Zs[(t4 * 4 + 1) * 257 + rr] = v.y;
            Zs[(t4 * 4 + 2) * 257 + rr] = v.z;
            Zs[(t4 * 4 + 3) * 257 + rr] = v.w;
        }
        __syncthreads();

        // ---- GEMM1: y[tt][og*8+oi] = sum_k Ws[o][k]*Zs[tt][k] ----
        float yacc[8];
        #pragma unroll
        for (int i = 0; i < 8; i++) yacc[i] = 0.f;
        #pragma unroll 4
        for (int k = 0; k < 256; k += 4) {
            float z0 = Zs[tt * 257 + k + 0];
            float z1 = Zs[tt * 257 + k + 1];
            float z2 = Zs[tt * 257 + k + 2];
            float z3 = Zs[tt * 257 + k + 3];
            #pragma unroll
            for (int oi = 0; oi < 8; oi++) {
                float4 w = *(const float4*)(Ws + (og * 8 + oi) * 256 + k);
                yacc[oi] += z0 * w.x;
                yacc[oi] += z1 * w.y;
                yacc[oi] += z2 * w.z;
                yacc[oi] += z3 * w.w;
            }
        }
        #pragma unroll
        for (int oi = 0; oi < 8; oi++) Ys[tt * 68 + og * 8 + oi] = yacc[oi];
        __syncthreads();

        // ---- GEMM2: acc[o] += Zs[t][r] * Ys[t][o] ----
        #pragma unroll 2
        for (int t = 0; t < 32; t++) {
            float zr = Zs[t * 257 + r];
            #pragma unroll
            for (int o4 = 0; o4 < 16; o4++) {
                float4 y = *(const float4*)(Ys + t * 68 + o4 * 4);
                acc[o4 * 4 + 0] += zr * y.x;
                acc[o4 * 4 + 1] += zr * y.y;
                acc[o4 * 4 + 2] += zr * y.z;
                acc[o4 * 4 + 3] += zr * y.w;
            }
        }
    }

    float* ep = g_epart + ((size_t)bc * Rr + r) * NC1;
    #pragma unroll
    for (int o4 = 0; o4 < 16; o4++) {
        float4 v = make_float4(acc[o4*4], acc[o4*4+1], acc[o4*4+2], acc[o4*4+3]);
        *(float4*)(ep + o4 * 4) = v;
    }
}

// ============================================================
// K3: sum partials over c, bias + leaky_relu -> e; pooled = mean over C1
// ============================================================
__global__ void k_reduce(const float* __restrict__ b_edge) {
    int br = blockIdx.x;                  // b*R + r
    int b = br >> 8, r = br & 255;
    int o = threadIdx.x;                  // 0..63
    float s = 0.f;
    const float* ep = g_epart + (((size_t)b * 16) * Rr + r) * NC1 + o;
    #pragma unroll
    for (int c = 0; c < 16; c++) s += ep[(size_t)c * Rr * NC1];
    s += b_edge[o];
    s = (s > 0.f) ? s : 0.01f * s;
    g_e[((size_t)b * Rr + r) * NC1 + o] = s;

    float v = s;
    #pragma unroll
    for (int off = 16; off > 0; off >>= 1) v += __shfl_down_sync(0xffffffffu, v, off);
    __shared__ float w2[2];
    if ((o & 31) == 0) w2[o >> 5] = v;
    __syncthreads();
    if (o == 0) g_pooled[b * Rr + r] = (w2[0] + w2[1]) * (1.0f / 64.0f);
}

// ============================================================
// K4: per b: MLP attention + NodeConv. Writes both outputs.
//   out[0 .. B*C2)           : o  [B,1,1,C2]
//   out[B*C2 .. B*C2 + B*R)  : att[B,R,1,1]
// ============================================================
__global__ void k_final(const float* __restrict__ W1, const float* __restrict__ b1,
                        const float* __restrict__ W2, const float* __restrict__ b2,
                        const float* __restrict__ W_node, const float* __restrict__ b_node,
                        float* __restrict__ out) {
    extern __shared__ float sm[];
    float* s_ae  = sm;                    // [64][257]  att*e transposed
    float* s_p   = sm + 64 * 257;         // 256
    float* s_h   = s_p + 256;             // 64
    float* s_att = s_h + 64;              // 256
    int b = blockIdx.x, tid = threadIdx.x;

    s_p[tid] = g_pooled[b * Rr + tid];
    __syncthreads();
    if (tid < 64) {
        float a = b1[tid];
        const float* w = W1 + tid * 256;
        #pragma unroll 8
        for (int rr = 0; rr < 256; rr++) a += w[rr] * s_p[rr];
        s_h[tid] = a > 0.f ? a : 0.f;
    }
    __syncthreads();
    {
        float a = b2[tid];
        const float* w = W2 + tid * 64;
        #pragma unroll
        for (int j = 0; j < 64; j++) a += w[j] * s_h[j];
        float att = 1.0f / (1.0f + expf(-a));
        s_att[tid] = att;
        out[Bsz * NC2 + b * Rr + tid] = att;
    }
    __syncthreads();

    const float* eb = g_e + (size_t)b * Rr * NC1;
    #pragma unroll
    for (int i = 0; i < 64; i++) {
        int idx = tid + i * 256;           // 0..16383
        int rr = idx >> 6, o = idx & 63;
        s_ae[o * 257 + rr] = eb[idx] * s_att[rr];
    }
    __syncthreads();

    int w = tid >> 5, lane = tid & 31;
    for (int it = 0; it < 16; it++) {
        int j = w + it * 8;
        const float* wn = W_node + (size_t)j * (NC1 * Rr);
        float a = 0.f;
        #pragma unroll 8
        for (int q = 0; q < 512; q++) {
            int idx = lane + q * 32;
            a += wn[idx] * s_ae[(idx >> 8) * 257 + (idx & 255)];
        }
        #pragma unroll
        for (int off = 16; off > 0; off >>= 1) a += __shfl_down_sync(0xffffffffu, a, off);
        if (lane == 0) {
            a += b_node[j];
            out[b * NC2 + j] = a > 0.f ? a : 0.01f * a;
        }
    }
}

// ============================================================
extern "C" void kernel_launch(void* const* d_in, const int* in_sizes, int n_in,
                              void* d_out, int out_size) {
    const float* x      = (const float*)d_in[0];
    const float* W_edge = (const float*)d_in[1];
    const float* b_edge = (const float*)d_in[2];
    const float* W1     = (const float*)d_in[3];
    const float* b1     = (const float*)d_in[4];
    const float* W2     = (const float*)d_in[5];
    const float* b2     = (const float*)d_in[6];
    const float* W_node = (const float*)d_in[7];
    const float* b_node = (const float*)d_in[8];
    float* out = (float*)d_out;

    const int smemB = (64 * 256 + 32 * 257 + 32 * 68) * 4;   // 107,136 B
    const int smemD = (64 * 257 + 256 + 64 + 256) * 4;       // 68,096 B
    cudaFuncSetAttribute(k_gemm,  cudaFuncAttributeMaxDynamicSharedMemorySize, smemB);
    cudaFuncSetAttribute(k_final, cudaFuncAttributeMaxDynamicSharedMemorySize, smemD);

    k_stats <<<Bsz * Rr, 256>>>(x);
    k_gemm  <<<Bsz * Cc, 256, smemB>>>(W_edge);
    k_reduce<<<Bsz * Rr, 64>>>(b_edge);
    k_final <<<Bsz, 256, smemD>>>(W1, b1, W2, b2, W_node, b_node, out);
}

// round 3
// speedup vs baseline: 1.4488x; 1.4488x over previous
#include <cuda_runtime.h>
#include <math.h>

#define Bsz 32
#define Rr  256
#define Tt  512
#define Cc  16
#define NC1 64
#define NC2 128

// ---- scratch (static __device__ per allocation rules) ----
__device__ float g_z[67108864];        // [B][C][R][T]  z = (x-mean)*rsqrt(sumsq), 268MB
__device__ float g_epart[8388608];     // [B*C][R][C1]  partial e per (b,c), 33.5MB
__device__ float g_e[524288];          // [B][R][C1]    e after bias+leakyrelu
__device__ float g_pooled[8192];       // [B][R]
__device__ float g_att[8192];          // [B][R]
__device__ float g_npart[262144];      // [64 splits][32 b][128 j]

__device__ __forceinline__ void fma2(unsigned long long &d,
                                     unsigned long long a,
                                     unsigned long long b) {
    asm("fma.rn.f32x2 %0, %1, %2, %0;" : "+l"(d) : "l"(a), "l"(b));
}
__device__ __forceinline__ unsigned long long packdup(float z) {
    unsigned long long zz;
    unsigned int zi = __float_as_uint(z);
    asm("mov.b64 %0, {%1,%1};" : "=l"(zz) : "r"(zi));
    return zz;
}

// ============================================================
// K1: per (b,r): load x[b,r,:,:] (512x16), compute per-c mean & inv-norm,
//     write z[b,c,r,:] transposed.
// ============================================================
__global__ void k_stats(const float* __restrict__ x) {
    int br = blockIdx.x;                 // b*R + r
    int b = br >> 8, r = br & 255;
    __shared__ float sx[Cc * 513];
    __shared__ float red[256];
    __shared__ float s_mean[Cc], s_inv[Cc];
    const float* xp = x + (size_t)br * (Tt * Cc);
    int tid = threadIdx.x;

    #pragma unroll
    for (int i = 0; i < 8; i++) {
        int idx4 = tid + i * 256;                 // 0..2047 float4s
        int t = idx4 >> 2;
        int c0 = (idx4 & 3) * 4;
        float4 v = *(const float4*)(xp + idx4 * 4);
        sx[(c0 + 0) * 513 + t] = v.x;
        sx[(c0 + 1) * 513 + t] = v.y;
        sx[(c0 + 2) * 513 + t] = v.z;
        sx[(c0 + 3) * 513 + t] = v.w;
    }
    __syncthreads();

    int c = tid & 15, seg = tid >> 4;
    float p = 0.f;
    #pragma unroll
    for (int u = 0; u < 32; u++) p += sx[c * 513 + seg * 32 + u];
    red[seg * 16 + c] = p;
    __syncthreads();
    if (tid < 16) {
        float s = 0.f;
        #pragma unroll
        for (int sg = 0; sg < 16; sg++) s += red[sg * 16 + tid];
        s_mean[tid] = s * (1.0f / Tt);
    }
    __syncthreads();

    float mc = s_mean[c];
    p = 0.f;
    #pragma unroll
    for (int u = 0; u < 32; u++) {
        float d = sx[c * 513 + seg * 32 + u] - mc;
        p += d * d;
    }
    red[seg * 16 + c] = p;
    __syncthreads();
    if (tid < 16) {
        float s = 0.f;
        #pragma unroll
        for (int sg = 0; sg < 16; sg++) s += red[sg * 16 + tid];
        s_inv[tid] = rsqrtf(s);
    }
    __syncthreads();

    int cw = tid >> 4, t0 = tid & 15;
    float m = s_mean[cw], inv = s_inv[cw];
    float* zo = g_z + (((size_t)b * Cc + cw) * Rr + r) * Tt;
    #pragma unroll
    for (int j = 0; j < 32; j++) {
        int t = t0 + j * 16;
        zo[t] = (sx[cw * 513 + t] - m) * inv;
    }
}

// ============================================================
// K2: per (b,c): stream z in T-chunks of 32.  f32x2 packed FMA.
//   GEMM1: y[t][o] = sum_k WsT[k][o] * z[k][t]
//   GEMM2: epart[r][o] += sum_t z[r][t] * y[t][o]
// smem: WsT[256][68] + Zs[32][257] + Ys[32][68]  = 111,232 B
// ============================================================
__global__ __launch_bounds__(256, 2) void k_gemm(const float* __restrict__ W_edge) {
    extern __shared__ float sm[];
    float* WsT = sm;                      // [256 k][68] (o fastest)
    float* Zs  = sm + 256 * 68;           // [32 t][257] (r fastest)
    float* Ys  = Zs + 32 * 257;           // [32 t][68]  (o fastest)
    int bc = blockIdx.x;                  // b*16 + c
    int c = bc & 15;
    int tid = threadIdx.x;
    const float* zb = g_z + (size_t)bc * (Rr * Tt);

    // Load W_edge[:, c, :] -> WsT[k][o]
    #pragma unroll
    for (int i = 0; i < 16; i++) {
        int idx4 = tid + i * 256;          // 0..4095
        int o = idx4 >> 6, k4 = idx4 & 63;
        float4 v = *(const float4*)(W_edge + ((size_t)o * Cc + c) * Rr + k4 * 4);
        WsT[(k4 * 4 + 0) * 68 + o] = v.x;
        WsT[(k4 * 4 + 1) * 68 + o] = v.y;
        WsT[(k4 * 4 + 2) * 68 + o] = v.z;
        WsT[(k4 * 4 + 3) * 68 + o] = v.w;
    }

    unsigned long long acc2[32];
    #pragma unroll
    for (int o = 0; o < 32; o++) acc2[o] = 0ull;

    int tt = tid & 31;        // t index for GEMM1 (lane)
    int og = tid >> 5;        // o-group (warp id), 8 o's each
    int r = tid;              // row owned in GEMM2

    for (int ch = 0; ch < 16; ch++) {
        __syncthreads();
        // ---- fill Zs[t][r] = z[b,c,r, ch*32+t] ----
        #pragma unroll
        for (int i = 0; i < 8; i++) {
            int idx4 = tid + i * 256;      // 0..2047
            int rr = idx4 >> 3, t4 = idx4 & 7;
            float4 v = *(const float4*)(zb + rr * Tt + ch * 32 + t4 * 4);
            Zs[(t4 * 4 + 0) * 257 + rr] = v.x;
            Zs[(t4 * 4 + 1) * 257 + rr] = v.y;
            Zs[(t4 * 4 + 2) * 257 + rr] = v.z;
            Zs[(t4 * 4 + 3) * 257 + rr] = v.w;
        }
        __syncthreads();

        // ---- GEMM1: y[tt][og*8+oi] = sum_k WsT[k][o] * Zs[tt][k] ----
        {
            unsigned long long y2[4];
            #pragma unroll
            for (int i = 0; i < 4; i++) y2[i] = 0ull;
            #pragma unroll 4
            for (int k = 0; k < 256; k++) {
                unsigned long long zz = packdup(Zs[tt * 257 + k]);
                const ulonglong2* wp = (const ulonglong2*)(WsT + k * 68 + og * 8);
                ulonglong2 wA = wp[0];
                ulonglong2 wB = wp[1];
                fma2(y2[0], zz, wA.x);
                fma2(y2[1], zz, wA.y);
                fma2(y2[2], zz, wB.x);
                fma2(y2[3], zz, wB.y);
            }
            ulonglong2* yp = (ulonglong2*)(Ys + tt * 68 + og * 8);
            ulonglong2 s0; s0.x = y2[0]; s0.y = y2[1];
            ulonglong2 s1; s1.x = y2[2]; s1.y = y2[3];
            yp[0] = s0;
            yp[1] = s1;
        }
        __syncthreads();

        // ---- GEMM2: acc[o] += Zs[t][r] * Ys[t][o] ----
        #pragma unroll 2
        for (int t = 0; t < 32; t++) {
            unsigned long long zz = packdup(Zs[t * 257 + r]);
            const ulonglong2* yp = (const ulonglong2*)(Ys + t * 68);
            #pragma unroll
            for (int g = 0; g < 16; g++) {
                ulonglong2 y = yp[g];
                fma2(acc2[2 * g + 0], zz, y.x);
                fma2(acc2[2 * g + 1], zz, y.y);
            }
        }
    }

    float* ep = g_epart + ((size_t)bc * Rr + r) * NC1;
    #pragma unroll
    for (int g = 0; g < 16; g++) {
        ulonglong2 st; st.x = acc2[2 * g]; st.y = acc2[2 * g + 1];
        *(ulonglong2*)(ep + g * 4) = st;
    }
}

// ============================================================
// K3: sum partials over c, bias + leaky_relu -> e; pooled = mean over C1
// ============================================================
__global__ void k_reduce(const float* __restrict__ b_edge) {
    int br = blockIdx.x;                  // b*R + r
    int b = br >> 8, r = br & 255;
    int o = threadIdx.x;                  // 0..63
    float s = 0.f;
    const float* ep = g_epart + (((size_t)b * 16) * Rr + r) * NC1 + o;
    #pragma unroll
    for (int c = 0; c < 16; c++) s += ep[(size_t)c * Rr * NC1];
    s += b_edge[o];
    s = (s > 0.f) ? s : 0.01f * s;
    g_e[((size_t)b * Rr + r) * NC1 + o] = s;

    float v = s;
    #pragma unroll
    for (int off = 16; off > 0; off >>= 1) v += __shfl_down_sync(0xffffffffu, v, off);
    __shared__ float w2[2];
    if ((o & 31) == 0) w2[o >> 5] = v;
    __syncthreads();
    if (o == 0) g_pooled[b * Rr + r] = (w2[0] + w2[1]) * (1.0f / 64.0f);
}

// ============================================================
// K4a: per b: MLP attention. Writes att part of output + g_att.
// ============================================================
__global__ void k_att(const float* __restrict__ W1, const float* __restrict__ b1,
                      const float* __restrict__ W2, const float* __restrict__ b2,
                      float* __restrict__ out) {
    __shared__ float s_p[256];
    __shared__ float s_h[64];
    int b = blockIdx.x, tid = threadIdx.x;

    s_p[tid] = g_pooled[b * Rr + tid];
    __syncthreads();
    if (tid < 64) {
        float a = b1[tid];
        const float* w = W1 + tid * 256;
        #pragma unroll 8
        for (int rr = 0; rr < 256; rr++) a += w[rr] * s_p[rr];
        s_h[tid] = a > 0.f ? a : 0.f;
    }
    __syncthreads();
    {
        float a = b2[tid];
        const float* w = W2 + tid * 64;
        #pragma unroll
        for (int j = 0; j < 64; j++) a += w[j] * s_h[j];
        float att = 1.0f / (1.0f + expf(-a));
        g_att[b * Rr + tid] = att;
        out[Bsz * NC2 + b * Rr + tid] = att;
    }
}

// ============================================================
// K4b: NodeConv split-K. 64 blocks, each owns 4 r's.
//   partial[j][b] = sum_{rr,o} W_node[j][o][r0+rr] * e[b][r0+rr][o] * att[b][r0+rr]
// ============================================================
__global__ __launch_bounds__(256) void k_node(const float* __restrict__ W_node) {
    __shared__ float sae[32 * 256];       // [b][o][rr]  (rr fastest, 4)
    __shared__ float s_att[128];          // [b][rr]
    int blk = blockIdx.x;
    int r0 = blk * 4;
    int tid = threadIdx.x;

    if (tid < 128) {
        int b = tid >> 2, rr = tid & 3;
        s_att[tid] = g_att[b * Rr + r0 + rr];
    }
    __syncthreads();

    #pragma unroll
    for (int i = 0; i < 8; i++) {
        int idx4 = tid + i * 256;          // 0..2047 (float4 over o)
        int b = idx4 >> 6, rr = (idx4 >> 4) & 3, o4 = idx4 & 15;
        float4 v = *(const float4*)(g_e + ((size_t)(b * Rr) + r0 + rr) * NC1 + o4 * 4);
        float a = s_att[b * 4 + rr];
        sae[b * 256 + (o4 * 4 + 0) * 4 + rr] = v.x * a;
        sae[b * 256 + (o4 * 4 + 1) * 4 + rr] = v.y * a;
        sae[b * 256 + (o4 * 4 + 2) * 4 + rr] = v.z * a;
        sae[b * 256 + (o4 * 4 + 3) * 4 + rr] = v.w * a;
    }
    __syncthreads();

    int j = tid >> 1, bh = tid & 1;       // j 0..127, 16 b's each
    unsigned long long acc2[16];
    #pragma unroll
    for (int i = 0; i < 16; i++) acc2[i] = 0ull;

    const float* wj = W_node + (size_t)j * (NC1 * Rr) + r0;
    #pragma unroll 4
    for (int o = 0; o < 64; o++) {
        ulonglong2 w = *(const ulonglong2*)(wj + o * Rr);  // (r0,r0+1),(r0+2,r0+3)
        const float* base = sae + bh * 16 * 256 + o * 4;
        #pragma unroll
        for (int bi = 0; bi < 16; bi++) {
            ulonglong2 ae = *(const ulonglong2*)(base + bi * 256);
            fma2(acc2[bi], w.x, ae.x);
            fma2(acc2[bi], w.y, ae.y);
        }
    }

    #pragma unroll
    for (int bi = 0; bi < 16; bi++) {
        float2 p = *(float2*)&acc2[bi];
        int b = bh * 16 + bi;
        g_npart[((size_t)blk * 32 + b) * NC2 + j] = p.x + p.y;
    }
}

// ============================================================
// K4c: reduce 64 split-K partials, bias + leaky_relu -> out
// ============================================================
__global__ void k_nred(const float* __restrict__ b_node, float* __restrict__ out) {
    int b = blockIdx.x, j = threadIdx.x;  // 32 blocks x 128 threads
    float s = 0.f;
    #pragma unroll 8
    for (int sp = 0; sp < 64; sp++)
        s += g_npart[((size_t)sp * 32 + b) * NC2 + j];
    s += b_node[j];
    out[b * NC2 + j] = s > 0.f ? s : 0.01f * s;
}

// ============================================================
extern "C" void kernel_launch(void* const* d_in, const int* in_sizes, int n_in,
                              void* d_out, int out_size) {
    const float* x      = (const float*)d_in[0];
    const float* W_edge = (const float*)d_in[1];
    const float* b_edge = (const float*)d_in[2];
    const float* W1     = (const float*)d_in[3];
    const float* b1     = (const float*)d_in[4];
    const float* W2     = (const float*)d_in[5];
    const float* b2     = (const float*)d_in[6];
    const float* W_node = (const float*)d_in[7];
    const float* b_node = (const float*)d_in[8];
    float* out = (float*)d_out;

    const int smemB = (256 * 68 + 32 * 257 + 32 * 68) * 4;   // 111,232 B
    cudaFuncSetAttribute(k_gemm, cudaFuncAttributeMaxDynamicSharedMemorySize, smemB);

    k_stats <<<Bsz * Rr, 256>>>(x);
    k_gemm  <<<Bsz * Cc, 256, smemB>>>(W_edge);
    k_reduce<<<Bsz * Rr, 64>>>(b_edge);
    k_att   <<<Bsz, 256>>>(W1, b1, W2, b2, out);
    k_node  <<<64, 256>>>(W_node);
    k_nred  <<<Bsz, 128>>>(b_node, out);
}

// round 6
// speedup vs baseline: 2.0558x; 1.4189x over previous
#include <cuda_runtime.h>
#include <math.h>

#define Bsz 32
#define Rr  256
#define Tt  512
#define Cc  16
#define NC1 64
#define NC2 128

// ---- scratch (static __device__ per allocation rules) ----
__device__ float g_z[67108864];        // [B*C][R][T]  z = (x-mean)*rsqrt(sumsq), 256MB
__device__ float g_y[16777216];        // [B*C][C1][T]  y, 64MB
__device__ float g_epart[4194304];     // [8 cg][32 b][256 r][64 o]
__device__ float g_e[524288];          // [B][R][C1]
__device__ float g_pooled[8192];       // [B][R]
__device__ float g_att[8192];          // [B][R]
__device__ float g_npart[262144];      // [64 splits][32 b][128 j]

__device__ __forceinline__ void fma2(unsigned long long &d,
                                     unsigned long long a,
                                     unsigned long long b) {
    asm("fma.rn.f32x2 %0, %1, %2, %0;" : "+l"(d) : "l"(a), "l"(b));
}
__device__ __forceinline__ unsigned long long packdup(float z) {
    unsigned long long zz;
    unsigned int zi = __float_as_uint(z);
    asm("mov.b64 %0, {%1,%1};" : "=l"(zz) : "r"(zi));
    return zz;
}

// ============================================================
// K1: per (b,r): stats + write z[bc][r][t]
// ============================================================
__global__ void k_stats(const float* __restrict__ x) {
    int br = blockIdx.x;                 // b*R + r
    int b = br >> 8, r = br & 255;
    __shared__ __align__(16) float sx[Cc * 513];
    __shared__ float red[256];
    __shared__ float s_mean[Cc], s_inv[Cc];
    const float* xp = x + (size_t)br * (Tt * Cc);
    int tid = threadIdx.x;

    #pragma unroll
    for (int i = 0; i < 8; i++) {
        int idx4 = tid + i * 256;
        int t = idx4 >> 2;
        int c0 = (idx4 & 3) * 4;
        float4 v = *(const float4*)(xp + idx4 * 4);
        sx[(c0 + 0) * 513 + t] = v.x;
        sx[(c0 + 1) * 513 + t] = v.y;
        sx[(c0 + 2) * 513 + t] = v.z;
        sx[(c0 + 3) * 513 + t] = v.w;
    }
    __syncthreads();

    int c = tid & 15, seg = tid >> 4;
    float p = 0.f;
    #pragma unroll
    for (int u = 0; u < 32; u++) p += sx[c * 513 + seg * 32 + u];
    red[seg * 16 + c] = p;
    __syncthreads();
    if (tid < 16) {
        float s = 0.f;
        #pragma unroll
        for (int sg = 0; sg < 16; sg++) s += red[sg * 16 + tid];
        s_mean[tid] = s * (1.0f / Tt);
    }
    __syncthreads();

    float mc = s_mean[c];
    p = 0.f;
    #pragma unroll
    for (int u = 0; u < 32; u++) {
        float d = sx[c * 513 + seg * 32 + u] - mc;
        p += d * d;
    }
    red[seg * 16 + c] = p;
    __syncthreads();
    if (tid < 16) {
        float s = 0.f;
        #pragma unroll
        for (int sg = 0; sg < 16; sg++) s += red[sg * 16 + tid];
        s_inv[tid] = rsqrtf(s);
    }
    __syncthreads();

    int cw = tid >> 4, t0 = tid & 15;
    float m = s_mean[cw], inv = s_inv[cw];
    float* zo = g_z + (((size_t)b * Cc + cw) * Rr + r) * Tt;
    #pragma unroll
    for (int j = 0; j < 32; j++) {
        int t = t0 + j * 16;
        zo[t] = (sx[cw * 513 + t] - m) * inv;
    }
}

// ============================================================
// K2a: y[bc][o][t] = sum_r W_edge[o][c][r] * z[bc][r][t]
// grid 1024 = bc*2 + ttile; block 256; thread tile 8o x 8t.
// ============================================================
__global__ __launch_bounds__(256, 2) void k_y(const float* __restrict__ W_edge) {
    __shared__ __align__(16) float Ws[32 * 68];     // [32 r][68] (o fastest)
    __shared__ __align__(16) float Zs[32 * 260];    // [32 r][260] (t fastest)
    int bc = blockIdx.x >> 1;
    int tt = blockIdx.x & 1;
    int tbase = tt * 256;
    int c = bc & 15;
    int tid = threadIdx.x;
    int og = tid >> 5, lane = tid & 31;
    int o0 = og * 8;
    int ta = lane * 4;
    const float* zb = g_z + (size_t)bc * (Rr * Tt);

    unsigned long long acc2[32];   // [oi 8][q 4]
    #pragma unroll
    for (int i = 0; i < 32; i++) acc2[i] = 0ull;

    for (int kb = 0; kb < 8; kb++) {
        __syncthreads();
        // fill Ws[r][o] for r in [kb*32, kb*32+32)
        #pragma unroll
        for (int i = 0; i < 2; i++) {
            int idx4 = tid + i * 256;            // 0..511
            int o = idx4 >> 3, r4 = idx4 & 7;
            float4 v = *(const float4*)(W_edge + ((size_t)o * Cc + c) * Rr + kb * 32 + r4 * 4);
            Ws[(r4 * 4 + 0) * 68 + o] = v.x;
            Ws[(r4 * 4 + 1) * 68 + o] = v.y;
            Ws[(r4 * 4 + 2) * 68 + o] = v.z;
            Ws[(r4 * 4 + 3) * 68 + o] = v.w;
        }
        // fill Zs[r][t] for 32 r x 256 t (direct, coalesced)
        #pragma unroll
        for (int i = 0; i < 8; i++) {
            int idx4 = tid + i * 256;            // 0..2047
            int rl = idx4 >> 6, t4 = idx4 & 63;
            float4 v = *(const float4*)(zb + (size_t)(kb * 32 + rl) * Tt + tbase + t4 * 4);
            *(float4*)(Zs + rl * 260 + t4 * 4) = v;
        }
        __syncthreads();

        #pragma unroll 2
        for (int k = 0; k < 32; k++) {
            float4 wv0 = *(const float4*)(Ws + k * 68 + o0);
            float4 wv1 = *(const float4*)(Ws + k * 68 + o0 + 4);
            ulonglong2 zA = *(const ulonglong2*)(Zs + k * 260 + ta);
            ulonglong2 zB = *(const ulonglong2*)(Zs + k * 260 + 128 + ta);
            unsigned long long zq0 = zA.x, zq1 = zA.y, zq2 = zB.x, zq3 = zB.y;
            unsigned long long wd[8];
            wd[0] = packdup(wv0.x); wd[1] = packdup(wv0.y);
            wd[2] = packdup(wv0.z); wd[3] = packdup(wv0.w);
            wd[4] = packdup(wv1.x); wd[5] = packdup(wv1.y);
            wd[6] = packdup(wv1.z); wd[7] = packdup(wv1.w);
            #pragma unroll
            for (int oi = 0; oi < 8; oi++) {
                fma2(acc2[oi * 4 + 0], wd[oi], zq0);
                fma2(acc2[oi * 4 + 1], wd[oi], zq1);
                fma2(acc2[oi * 4 + 2], wd[oi], zq2);
                fma2(acc2[oi * 4 + 3], wd[oi], zq3);
            }
        }
    }

    float* yb = g_y + (size_t)bc * (NC1 * Tt);
    #pragma unroll
    for (int oi = 0; oi < 8; oi++) {
        ulonglong2 s0; s0.x = acc2[oi * 4 + 0]; s0.y = acc2[oi * 4 + 1];
        ulonglong2 s1; s1.x = acc2[oi * 4 + 2]; s1.y = acc2[oi * 4 + 3];
        *(ulonglong2*)(yb + (size_t)(o0 + oi) * Tt + tbase + ta) = s0;
        *(ulonglong2*)(yb + (size_t)(o0 + oi) * Tt + tbase + 128 + ta) = s1;
    }
}

// ============================================================
// K2b: epart[cg][b][r][o] = sum_{c in cg} sum_t z[b,c,r,t]*y[b,c,o,t]
// grid 256 = b*8 + cg (2 c's each); block 256; thread tile 8r x 8o.
// ============================================================
__global__ __launch_bounds__(256, 2) void k_e() {
    __shared__ __align__(16) float Zs[32 * 260];    // [32 t][260] (r fastest)
    __shared__ __align__(16) float Ys[32 * 68];     // [32 t][68]  (o fastest)
    int b = blockIdx.x >> 3;
    int cg = blockIdx.x & 7;
    int tid = threadIdx.x;
    int og = tid >> 5, rg = tid & 31;
    int o0 = og * 8;
    int ra = rg * 4;

    unsigned long long acc2[32];   // [ri 8][op 4]
    #pragma unroll
    for (int i = 0; i < 32; i++) acc2[i] = 0ull;

    for (int ci = 0; ci < 2; ci++) {
        int c = cg * 2 + ci;
        const float* zb = g_z + ((size_t)b * Cc + c) * (Rr * Tt);
        const float* yb = g_y + ((size_t)b * Cc + c) * (NC1 * Tt);
        for (int tc = 0; tc < 16; tc++) {
            __syncthreads();
            // fill Zs[t][r]: 256 r x 32 t (transpose)
            #pragma unroll
            for (int i = 0; i < 8; i++) {
                int idx4 = tid + i * 256;          // 0..2047
                int r = idx4 >> 3, t4 = idx4 & 7;
                float4 v = *(const float4*)(zb + (size_t)r * Tt + tc * 32 + t4 * 4);
                Zs[(t4 * 4 + 0) * 260 + r] = v.x;
                Zs[(t4 * 4 + 1) * 260 + r] = v.y;
                Zs[(t4 * 4 + 2) * 260 + r] = v.z;
                Zs[(t4 * 4 + 3) * 260 + r] = v.w;
            }
            // fill Ys[t][o]: 64 o x 32 t (transpose)
            #pragma unroll
            for (int i = 0; i < 2; i++) {
                int idx4 = tid + i * 256;          // 0..511
                int o = idx4 >> 3, t4 = idx4 & 7;
                float4 v = *(const float4*)(yb + (size_t)o * Tt + tc * 32 + t4 * 4);
                Ys[(t4 * 4 + 0) * 68 + o] = v.x;
                Ys[(t4 * 4 + 1) * 68 + o] = v.y;
                Ys[(t4 * 4 + 2) * 68 + o] = v.z;
                Ys[(t4 * 4 + 3) * 68 + o] = v.w;
            }
            __syncthreads();

            #pragma unroll 2
            for (int t = 0; t < 32; t++) {
                float4 zA = *(const float4*)(Zs + t * 260 + ra);
                float4 zB = *(const float4*)(Zs + t * 260 + 128 + ra);
                ulonglong2 yA = *(const ulonglong2*)(Ys + t * 68 + o0);
                ulonglong2 yB = *(const ulonglong2*)(Ys + t * 68 + o0 + 4);
                unsigned long long yv0 = yA.x, yv1 = yA.y, yv2 = yB.x, yv3 = yB.y;
                unsigned long long zd[8];
                zd[0] = packdup(zA.x); zd[1] = packdup(zA.y);
                zd[2] = packdup(zA.z); zd[3] = packdup(zA.w);
                zd[4] = packdup(zB.x); zd[5] = packdup(zB.y);
                zd[6] = packdup(zB.z); zd[7] = packdup(zB.w);
                #pragma unroll
                for (int ri = 0; ri < 8; ri++) {
                    fma2(acc2[ri * 4 + 0], zd[ri], yv0);
                    fma2(acc2[ri * 4 + 1], zd[ri], yv1);
                    fma2(acc2[ri * 4 + 2], zd[ri], yv2);
                    fma2(acc2[ri * 4 + 3], zd[ri], yv3);
                }
            }
        }
    }

    #pragma unroll
    for (int ri = 0; ri < 8; ri++) {
        int r = (ri < 4) ? (ra + ri) : (128 + ra + ri - 4);
        ulonglong2 s0; s0.x = acc2[ri * 4 + 0]; s0.y = acc2[ri * 4 + 1];
        ulonglong2 s1; s1.x = acc2[ri * 4 + 2]; s1.y = acc2[ri * 4 + 3];
        float* ep = g_epart + (((size_t)cg * Bsz + b) * Rr + r) * NC1 + o0;
        *(ulonglong2*)(ep) = s0;
        *(ulonglong2*)(ep + 4) = s1;
    }
}

// ============================================================
// K3: sum 8 split-K partials, bias + leaky_relu -> e; pooled
// ============================================================
__global__ void k_reduce(const float* __restrict__ b_edge) {
    int br = blockIdx.x;                  // b*R + r
    int b = br >> 8, r = br & 255;
    int o = threadIdx.x;                  // 0..63
    float s = 0.f;
    #pragma unroll
    for (int cg = 0; cg < 8; cg++)
        s += g_epart[(((size_t)cg * Bsz + b) * Rr + r) * NC1 + o];
    s += b_edge[o];
    s = (s > 0.f) ? s : 0.01f * s;
    g_e[((size_t)b * Rr + r) * NC1 + o] = s;

    float v = s;
    #pragma unroll
    for (int off = 16; off > 0; off >>= 1) v += __shfl_down_sync(0xffffffffu, v, off);
    __shared__ float w2[2];
    if ((o & 31) == 0) w2[o >> 5] = v;
    __syncthreads();
    if (o == 0) g_pooled[b * Rr + r] = (w2[0] + w2[1]) * (1.0f / 64.0f);
}

// ============================================================
// K4a: per b: MLP attention (parallelized layer-1).
// ============================================================
__global__ void k_att(const float* __restrict__ W1, const float* __restrict__ b1,
                      const float* __restrict__ W2, const float* __restrict__ b2,
                      float* __restrict__ out) {
    __shared__ __align__(16) float s_p[256];
    __shared__ __align__(16) float s_h[64];
    int b = blockIdx.x, tid = threadIdx.x;

    s_p[tid] = g_pooled[b * Rr + tid];
    __syncthreads();
    {
        int hi = tid >> 2, q = tid & 3;
        const float* w = W1 + hi * 256 + q * 64;
        float a = 0.f;
        #pragma unroll
        for (int j = 0; j < 16; j++) {
            float4 wv = *(const float4*)(w + j * 4);
            float4 pv = *(const float4*)(s_p + q * 64 + j * 4);
            a += wv.x * pv.x + wv.y * pv.y + wv.z * pv.z + wv.w * pv.w;
        }
        a += __shfl_xor_sync(0xffffffffu, a, 1);
        a += __shfl_xor_sync(0xffffffffu, a, 2);
        if (q == 0) {
            a += b1[hi];
            s_h[hi] = a > 0.f ? a : 0.f;
        }
    }
    __syncthreads();
    {
        float a = b2[tid];
        const float* w = W2 + tid * 64;
        #pragma unroll
        for (int j = 0; j < 16; j++) {
            float4 wv = *(const float4*)(w + j * 4);
            float4 hv = *(const float4*)(s_h + j * 4);
            a += wv.x * hv.x + wv.y * hv.y + wv.z * hv.z + wv.w * hv.w;
        }
        float att = 1.0f / (1.0f + expf(-a));
        g_att[b * Rr + tid] = att;
        out[Bsz * NC2 + b * Rr + tid] = att;
    }
}

// ============================================================
// K4b: NodeConv split-K. 64 blocks, each owns 4 r's.
// ============================================================
__global__ __launch_bounds__(256) void k_node(const float* __restrict__ W_node) {
    __shared__ __align__(16) float sae[32 * 256];       // [b][o][rr]
    __shared__ float s_att[128];
    int blk = blockIdx.x;
    int r0 = blk * 4;
    int tid = threadIdx.x;

    if (tid < 128) {
        int b = tid >> 2, rr = tid & 3;
        s_att[tid] = g_att[b * Rr + r0 + rr];
    }
    __syncthreads();

    #pragma unroll
    for (int i = 0; i < 8; i++) {
        int idx4 = tid + i * 256;
        int b = idx4 >> 6, rr = (idx4 >> 4) & 3, o4 = idx4 & 15;
        float4 v = *(const float4*)(g_e + ((size_t)(b * Rr) + r0 + rr) * NC1 + o4 * 4);
        float a = s_att[b * 4 + rr];
        sae[b * 256 + (o4 * 4 + 0) * 4 + rr] = v.x * a;
        sae[b * 256 + (o4 * 4 + 1) * 4 + rr] = v.y * a;
        sae[b * 256 + (o4 * 4 + 2) * 4 + rr] = v.z * a;
        sae[b * 256 + (o4 * 4 + 3) * 4 + rr] = v.w * a;
    }
    __syncthreads();

    int j = tid >> 1, bh = tid & 1;
    unsigned long long acc2[16];
    #pragma unroll
    for (int i = 0; i < 16; i++) acc2[i] = 0ull;

    const float* wj = W_node + (size_t)j * (NC1 * Rr) + r0;
    #pragma unroll 4
    for (int o = 0; o < 64; o++) {
        ulonglong2 w = *(const ulonglong2*)(wj + o * Rr);
        const float* base = sae + bh * 16 * 256 + o * 4;
        #pragma unroll
        for (int bi = 0; bi < 16; bi++) {
            ulonglong2 ae = *(const ulonglong2*)(base + bi * 256);
            fma2(acc2[bi], w.x, ae.x);
            fma2(acc2[bi], w.y, ae.y);
        }
    }

    #pragma unroll
    for (int bi = 0; bi < 16; bi++) {
        float2 p = *(float2*)&acc2[bi];
        int b = bh * 16 + bi;
        g_npart[((size_t)blk * 32 + b) * NC2 + j] = p.x + p.y;
    }
}

// ============================================================
// K4c: reduce 64 split-K partials, bias + leaky_relu -> out
// ============================================================
__global__ void k_nred(const float* __restrict__ b_node, float* __restrict__ out) {
    int b = blockIdx.x, j = threadIdx.x;
    float s = 0.f;
    #pragma unroll 8
    for (int sp = 0; sp < 64; sp++)
        s += g_npart[((size_t)sp * 32 + b) * NC2 + j];
    s += b_node[j];
    out[b * NC2 + j] = s > 0.f ? s : 0.01f * s;
}

// ============================================================
extern "C" void kernel_launch(void* const* d_in, const int* in_sizes, int n_in,
                              void* d_out, int out_size) {
    const float* x      = (const float*)d_in[0];
    const float* W_edge = (const float*)d_in[1];
    const float* b_edge = (const float*)d_in[2];
    const float* W1     = (const float*)d_in[3];
    const float* b1     = (const float*)d_in[4];
    const float* W2     = (const float*)d_in[5];
    const float* b2     = (const float*)d_in[6];
    const float* W_node = (const float*)d_in[7];
    const float* b_node = (const float*)d_in[8];
    float* out = (float*)d_out;

    k_stats <<<Bsz * Rr, 256>>>(x);
    k_y     <<<Bsz * Cc * 2, 256>>>(W_edge);
    k_e     <<<Bsz * 8, 256>>>();
    k_reduce<<<Bsz * Rr, 64>>>(b_edge);
    k_att   <<<Bsz, 256>>>(W1, b1, W2, b2, out);
    k_node  <<<64, 256>>>(W_node);
    k_nred  <<<Bsz, 128>>>(b_node, out);
}